// round 4
// baseline (speedup 1.0000x reference)
#include <cuda_runtime.h>
#include <cuda_bf16.h>
#include <stdint.h>

#define B_ 16
#define Q_ 100
#define G_ 16384
#define T_ 50
#define L_ 21
#define NCH 18
#define KB 64          // k elements per stage
#define MP 112         // padded M (7 warps x 16)
#define NP 56          // padded N (7 n-tiles x 8)
#define NT 224         // threads (7 warps)

// ---------------- device scratch (module statics, allocation-free) ----------------
__device__ float g_P1[B_*NCH*MP*NP];     // partial dot(x, m)
__device__ float g_P2[B_*NCH*MP*NP];     // partial dot(sig(x), m)
__device__ float g_SnegP[B_*NCH*Q_];     // partial softplus row sums
__device__ float g_SsigP[B_*NCH*Q_];     // partial sigmoid row sums
__device__ float g_SmP[B_*NCH*T_];       // partial mask row sums
__device__ float g_Sneg[B_*Q_];
__device__ float g_Ssig[B_*Q_];
__device__ float g_Sm[B_*T_];

// ---------------- helpers ----------------
__device__ __forceinline__ uint32_t smem_u32(const void* p) {
    uint32_t a;
    asm("{ .reg .u64 t; cvta.to.shared.u64 t, %1; cvt.u32.u64 %0, t; }"
        : "=r"(a) : "l"(p));
    return a;
}
__device__ __forceinline__ uint32_t bf2(float lo, float hi) {
    uint32_t r;
    asm("cvt.rn.bf16x2.f32 %0, %1, %2;" : "=r"(r) : "f"(hi), "f"(lo));
    return r;
}
__device__ __forceinline__ float fast_tanh(float x) {
    float r;
    asm("tanh.approx.f32 %0, %1;" : "=f"(r) : "f"(x));
    return r;
}
__device__ __forceinline__ float fast_lg2(float x) {
    float r;
    asm("lg2.approx.f32 %0, %1;" : "=f"(r) : "f"(x));
    return r;
}
#define LDSM4(r0,r1,r2,r3,addr) \
    asm volatile("ldmatrix.sync.aligned.m8n8.x4.shared.b16 {%0,%1,%2,%3}, [%4];" \
        : "=r"(r0),"=r"(r1),"=r"(r2),"=r"(r3) : "r"(addr))
#define LDSM2(r0,r1,addr) \
    asm volatile("ldmatrix.sync.aligned.m8n8.x2.shared.b16 {%0,%1}, [%2];" \
        : "=r"(r0),"=r"(r1) : "r"(addr))
#define MMA16816(d,a,b) \
    asm volatile("mma.sync.aligned.m16n8k16.row.col.f32.bf16.bf16.f32 " \
        "{%0,%1,%2,%3},{%4,%5,%6,%7},{%8,%9},{%0,%1,%2,%3};" \
        : "+f"((d)[0]),"+f"((d)[1]),"+f"((d)[2]),"+f"((d)[3]) \
        : "r"((a)[0]),"r"((a)[1]),"r"((a)[2]),"r"((a)[3]),"r"((b)[0]),"r"((b)[1]))

// ---------------- kernel 1: fused convert + dual HMMA GEMM ----------------
// grid = (NCH, B_), block = 224, 2 CTAs/SM. CTA tile: M=112, N=56, K-chunk.
__global__ void __launch_bounds__(NT, 2)
pm_mma_kernel(const float* __restrict__ xg, const float* __restrict__ mg)
{
    __shared__ __align__(1024) __nv_bfloat16 sA[MP*KB];   // x    14336 B
    __shared__ __align__(1024) __nv_bfloat16 sS[MP*KB];   // sig  14336 B
    __shared__ __align__(1024) __nv_bfloat16 sB[NP*KB];   // m     7168 B

    const int b   = blockIdx.y;
    const int c   = blockIdx.x;
    const int tid = threadIdx.x;
    const int wid = tid >> 5;
    const int lid = tid & 31;

    // K split: 256 KB-units over 18 chunks -> 4x15 + 14x14
    const int nu = 14 + (c < 4 ? 1 : 0);
    const int u0 = c * 14 + (c < 4 ? c : 4);

    // zero smem once (pad rows stay zero)
    for (int i = tid; i < MP*KB/8; i += NT) {
        reinterpret_cast<uint4*>(sA)[i] = make_uint4(0,0,0,0);
        reinterpret_cast<uint4*>(sS)[i] = make_uint4(0,0,0,0);
    }
    for (int i = tid; i < NP*KB/8; i += NT)
        reinterpret_cast<uint4*>(sB)[i] = make_uint4(0,0,0,0);
    __syncthreads();

    const uint32_t sA32 = smem_u32(sA);
    const uint32_t sS32 = smem_u32(sS);
    const uint32_t sB32 = smem_u32(sB);

    // ---- ldmatrix address precompute ----
    const int mbase = wid * 16;
    const int arow  = mbase + (lid & 15);
    const uint32_t aoff  = (uint32_t)(arow * 128);
    const uint32_t axor  = (uint32_t)((arow & 7) << 4);
    const uint32_t akb0  = (uint32_t)((lid >> 4) << 4);      // 0 | 16
    const int bg = lid >> 3, br = lid & 7;
    const uint32_t bxor = (uint32_t)(br << 4);
    const uint32_t bkb0 = (uint32_t)((bg & 1) << 4);

    // ---- loader slot precompute ----
    const float* xb = xg + (size_t)b * Q_ * G_;
    const float* mb = mg + (size_t)b * T_ * G_;
    int xrow[8], xc4[8]; bool xact[8];
    #pragma unroll
    for (int j = 0; j < 8; j++) {
        int sl = tid + NT * j;
        xact[j] = sl < Q_ * (KB/4);
        xrow[j] = sl >> 4; xc4[j] = sl & 15;
    }
    int mrow[4], mc4[4]; bool mact[4];
    #pragma unroll
    for (int j = 0; j < 4; j++) {
        int sl = tid + NT * j;
        mact[j] = sl < T_ * (KB/4);
        mrow[j] = sl >> 4; mc4[j] = sl & 15;
    }

    float c1[7][4], c2[7][4];
    #pragma unroll
    for (int j = 0; j < 7; j++)
        #pragma unroll
        for (int u = 0; u < 4; u++) { c1[j][u] = 0.f; c2[j][u] = 0.f; }
    float aSP[8], aSG[8], aM[4];
    #pragma unroll
    for (int j = 0; j < 8; j++) { aSP[j] = 0.f; aSG[j] = 0.f; }
    #pragma unroll
    for (int j = 0; j < 4; j++) aM[j] = 0.f;

    // ---- prologue: prefetch stage 0 into registers ----
    float4 vx[8], vm[4];
    {
        const int k0 = u0 * KB;
        #pragma unroll
        for (int j = 0; j < 8; j++)
            if (xact[j])
                vx[j] = *reinterpret_cast<const float4*>(
                    xb + (size_t)xrow[j] * G_ + k0 + xc4[j] * 4);
        #pragma unroll
        for (int j = 0; j < 4; j++)
            if (mact[j])
                vm[j] = *reinterpret_cast<const float4*>(
                    mb + (size_t)mrow[j] * G_ + k0 + mc4[j] * 4);
    }

    for (int s = 0; s < nu; s++) {
        // ---- convert stage s (consumes vx/vm), then prefetch stage s+1 ----
        uint32_t pxa[8][2], pxs[8][2], pmm[4][2];
        #pragma unroll
        for (int j = 0; j < 8; j++) {
            if (!xact[j]) continue;
            float f[4] = { vx[j].x, vx[j].y, vx[j].z, vx[j].w };
            float sg[4];
            #pragma unroll
            for (int u = 0; u < 4; u++) {
                float x    = f[u];
                float t    = fast_tanh(0.5f * x);
                float sig  = fmaf(0.5f, t, 0.5f);
                float siga = fmaf(0.5f, fabsf(t), 0.5f);   // sigmoid(|x|)
                sg[u] = sig;
                aSG[j] += sig;
                aSP[j] += fmaxf(x, 0.f) - 0.69314718056f * fast_lg2(siga);
            }
            pxa[j][0] = bf2(f[0], f[1]);   pxa[j][1] = bf2(f[2], f[3]);
            pxs[j][0] = bf2(sg[0], sg[1]); pxs[j][1] = bf2(sg[2], sg[3]);
        }
        #pragma unroll
        for (int j = 0; j < 4; j++) {
            if (!mact[j]) continue;
            aM[j] += vm[j].x + vm[j].y + vm[j].z + vm[j].w;
            pmm[j][0] = bf2(vm[j].x, vm[j].y);
            pmm[j][1] = bf2(vm[j].z, vm[j].w);
        }

        // ---- prefetch next stage (latency hidden behind STS+syncs+MMA) ----
        if (s + 1 < nu) {
            const int kn = (u0 + s + 1) * KB;
            #pragma unroll
            for (int j = 0; j < 8; j++)
                if (xact[j])
                    vx[j] = *reinterpret_cast<const float4*>(
                        xb + (size_t)xrow[j] * G_ + kn + xc4[j] * 4);
            #pragma unroll
            for (int j = 0; j < 4; j++)
                if (mact[j])
                    vm[j] = *reinterpret_cast<const float4*>(
                        mb + (size_t)mrow[j] * G_ + kn + mc4[j] * 4);
        }

        __syncthreads();   // previous stage's ldmatrix reads complete

        // ---- STS with SW128 swizzle ----
        #pragma unroll
        for (int j = 0; j < 8; j++) {
            if (!xact[j]) continue;
            uint32_t off = (uint32_t)(xrow[j] * 128)
                         + (uint32_t)((xc4[j] * 8) ^ ((xrow[j] & 7) << 4));
            *reinterpret_cast<uint2*>(reinterpret_cast<char*>(sA) + off) =
                make_uint2(pxa[j][0], pxa[j][1]);
            *reinterpret_cast<uint2*>(reinterpret_cast<char*>(sS) + off) =
                make_uint2(pxs[j][0], pxs[j][1]);
        }
        #pragma unroll
        for (int j = 0; j < 4; j++) {
            if (!mact[j]) continue;
            uint32_t off = (uint32_t)(mrow[j] * 128)
                         + (uint32_t)((mc4[j] * 8) ^ ((mrow[j] & 7) << 4));
            *reinterpret_cast<uint2*>(reinterpret_cast<char*>(sB) + off) =
                make_uint2(pmm[j][0], pmm[j][1]);
        }
        __syncthreads();

        // ---- MMA: 4 k-steps x 7 n-tiles x 2 gemms ----
        #pragma unroll
        for (int ks = 0; ks < 4; ks++) {
            const uint32_t akb = (uint32_t)(ks * 32) + akb0;
            const uint32_t aad = aoff + (akb ^ axor);
            uint32_t ax[4], as2[4];
            LDSM4(ax[0],  ax[1],  ax[2],  ax[3],  sA32 + aad);
            LDSM4(as2[0], as2[1], as2[2], as2[3], sS32 + aad);

            uint32_t bf[7][2];
            #pragma unroll
            for (int p = 0; p < 3; p++) {
                int j = p * 2;
                int row = (j + (bg >> 1)) * 8 + br;
                uint32_t kb = (uint32_t)(ks * 32) + bkb0;
                uint32_t ad = (uint32_t)(row * 128) + (kb ^ bxor);
                LDSM4(bf[j][0], bf[j][1], bf[j+1][0], bf[j+1][1], sB32 + ad);
            }
            {   // n-tile 6
                int row = 48 + br;
                uint32_t kb = (uint32_t)(ks * 32) + (uint32_t)((bg & 1) << 4);
                uint32_t ad = (uint32_t)(row * 128) + (kb ^ bxor);
                LDSM2(bf[6][0], bf[6][1], sB32 + ad);
            }
            #pragma unroll
            for (int j = 0; j < 7; j++) {
                MMA16816(c1[j], ax,  bf[j]);
                MMA16816(c2[j], as2, bf[j]);
            }
        }
    }

    // ---- row-stat reduction (16 lanes per row -> shfl) ----
    #pragma unroll
    for (int j = 0; j < 8; j++) {
        if (!xact[j]) continue;          // warp-uniform
        float v1 = aSP[j], v2 = aSG[j];
        #pragma unroll
        for (int o = 8; o > 0; o >>= 1) {
            v1 += __shfl_xor_sync(0xffffffffu, v1, o);
            v2 += __shfl_xor_sync(0xffffffffu, v2, o);
        }
        if ((lid & 15) == 0) {
            g_SnegP[(b * NCH + c) * Q_ + xrow[j]] = v1;
            g_SsigP[(b * NCH + c) * Q_ + xrow[j]] = v2;
        }
    }
    #pragma unroll
    for (int j = 0; j < 4; j++) {
        if (!mact[j]) continue;
        float v = aM[j];
        #pragma unroll
        for (int o = 8; o > 0; o >>= 1)
            v += __shfl_xor_sync(0xffffffffu, v, o);
        if ((lid & 15) == 0)
            g_SmP[(b * NCH + c) * T_ + mrow[j]] = v;
    }

    // ---- C epilogue: direct stores (disjoint per CTA, padded layout) ----
    {
        const int r0 = mbase + (lid >> 2);
        const int cb = (lid & 3) * 2;
        float* p1 = g_P1 + ((size_t)((b * NCH + c) * MP + r0)) * NP;
        float* p2 = g_P2 + ((size_t)((b * NCH + c) * MP + r0)) * NP;
        #pragma unroll
        for (int j = 0; j < 7; j++) {
            int col = j * 8 + cb;
            *reinterpret_cast<float2*>(p1 + col)          = make_float2(c1[j][0], c1[j][1]);
            *reinterpret_cast<float2*>(p1 + 8*NP + col)   = make_float2(c1[j][2], c1[j][3]);
            *reinterpret_cast<float2*>(p2 + col)          = make_float2(c2[j][0], c2[j][1]);
            *reinterpret_cast<float2*>(p2 + 8*NP + col)   = make_float2(c2[j][2], c2[j][3]);
        }
    }
}

// ---------------- kernel 2: reduce row-stat partials ----------------
__global__ void stat_reduce_kernel() {
    int i = blockIdx.x * blockDim.x + threadIdx.x;
    if (i < B_*Q_) {
        int b = i / Q_, q = i % Q_;
        float s1 = 0.f, s2 = 0.f;
        #pragma unroll
        for (int c = 0; c < NCH; c++) {
            s1 += g_SnegP[(b * NCH + c) * Q_ + q];
            s2 += g_SsigP[(b * NCH + c) * Q_ + q];
        }
        g_Sneg[i] = s1; g_Ssig[i] = s2;
    } else if (i < B_*Q_ + B_*T_) {
        int k = i - B_*Q_;
        int b = k / T_, t = k % T_;
        float s = 0.f;
        #pragma unroll
        for (int c = 0; c < NCH; c++)
            s += g_SmP[(b * NCH + c) * T_ + t];
        g_Sm[k] = s;
    }
}

// ---------------- kernel 3: reduce C partials + class cost (t-pairs) ----------------
#define TPAIRS (T_/2)
__global__ void combine_kernel(const float* __restrict__ clsq,
                               const int* __restrict__ labw,
                               float* __restrict__ out)
{
    int idx = blockIdx.x * blockDim.x + threadIdx.x;
    if (idx >= B_*Q_*TPAIRS) return;
    int p = idx % TPAIRS;
    int q = (idx / TPAIRS) % Q_;
    int b = idx / (TPAIRS*Q_);
    int t0 = 2 * p;

    float2 D1 = make_float2(0.f, 0.f), D2 = make_float2(0.f, 0.f);
    #pragma unroll
    for (int c = 0; c < NCH; c++) {
        size_t o = ((size_t)((b * NCH + c) * MP + q)) * NP + t0;
        float2 v1 = *reinterpret_cast<const float2*>(g_P1 + o);
        float2 v2 = *reinterpret_cast<const float2*>(g_P2 + o);
        D1.x += v1.x; D1.y += v1.y;
        D2.x += v2.x; D2.y += v2.y;
    }

    // label dtype detect (int64 high words zero for labels < 2^31)
    bool is64 = true;
    #pragma unroll
    for (int j = 0; j < 8; j++) is64 &= (labw[2*j + 1] == 0);
    int li0 = b * T_ + t0;
    int l0 = is64 ? labw[2 * li0]       : labw[li0];
    int l1 = is64 ? labw[2 * (li0 + 1)] : labw[li0 + 1];

    const float* cl = clsq + (size_t)(b * Q_ + q) * L_;
    float mx = cl[0];
    #pragma unroll
    for (int k = 1; k < L_; k++) mx = fmaxf(mx, cl[k]);
    float ssum = 0.f;
    #pragma unroll
    for (int k = 0; k < L_; k++) ssum += __expf(cl[k] - mx);
    float inv = __fdividef(1.f, ssum);
    float prob0 = __expf(cl[l0] - mx) * inv;
    float prob1 = __expf(cl[l1] - mx) * inv;

    float Sneg = g_Sneg[b * Q_ + q];
    float Ssig = g_Ssig[b * Q_ + q];
    float Sm0  = g_Sm[li0];
    float Sm1  = g_Sm[li0 + 1];

    const float invG = 1.0f / (float)G_;
    float o0 = (Sneg - D1.x) * invG - prob0
             + 1.0f - (2.0f * D2.x + 1.0f) * __fdividef(1.f, Ssig + Sm0 + 1.0f);
    float o1 = (Sneg - D1.y) * invG - prob1
             + 1.0f - (2.0f * D2.y + 1.0f) * __fdividef(1.f, Ssig + Sm1 + 1.0f);
    *reinterpret_cast<float2*>(out + (size_t)(b * Q_ + q) * T_ + t0) =
        make_float2(o0, o1);
}

// ---------------- launch ----------------
extern "C" void kernel_launch(void* const* d_in, const int* in_sizes, int n_in,
                              void* d_out, int out_size)
{
    const float* x   = (const float*)d_in[0];   // [16,100,16384] f32
    const float* cq  = (const float*)d_in[1];   // [16,100,21]    f32
    const float* m   = (const float*)d_in[2];   // [16,50,16384]  f32
    const int*   lab = (const int*)d_in[3];     // [16,50] labels

    dim3 grid(NCH, B_);
    pm_mma_kernel<<<grid, NT>>>(x, m);

    stat_reduce_kernel<<<(B_*Q_ + B_*T_ + 255) / 256, 256>>>();

    combine_kernel<<<(B_*Q_*TPAIRS + 255) / 256, 256>>>(cq, lab, (float*)d_out);
}

// round 5
// speedup vs baseline: 1.6301x; 1.6301x over previous
#include <cuda_runtime.h>
#include <cuda_bf16.h>
#include <stdint.h>

#define B_ 16
#define Q_ 100
#define G_ 16384
#define T_ 50
#define L_ 21
#define NCH 18
#define KB 32          // k elements per stage (half of a 128B row; double-buffered)
#define MP 112         // padded M (7 warps x 16)
#define NP 56          // padded N (7 n-tiles x 8)
#define NT 224         // threads (7 warps)

// ---------------- device scratch (module statics, allocation-free) ----------------
__device__ float g_P1[B_*NCH*MP*NP];     // partial dot(x, m)
__device__ float g_P2[B_*NCH*MP*NP];     // partial dot(sig(x), m)
__device__ float g_SnegP[B_*NCH*Q_];     // partial softplus row sums
__device__ float g_SsigP[B_*NCH*Q_];     // partial sigmoid row sums
__device__ float g_SmP[B_*NCH*T_];       // partial mask row sums
__device__ float g_Sneg[B_*Q_];
__device__ float g_Ssig[B_*Q_];
__device__ float g_Sm[B_*T_];

// ---------------- helpers ----------------
__device__ __forceinline__ uint32_t smem_u32(const void* p) {
    uint32_t a;
    asm("{ .reg .u64 t; cvta.to.shared.u64 t, %1; cvt.u32.u64 %0, t; }"
        : "=r"(a) : "l"(p));
    return a;
}
__device__ __forceinline__ uint32_t bf2(float lo, float hi) {
    uint32_t r;
    asm("cvt.rn.bf16x2.f32 %0, %1, %2;" : "=r"(r) : "f"(hi), "f"(lo));
    return r;
}
__device__ __forceinline__ float fast_tanh(float x) {
    float r;
    asm("tanh.approx.f32 %0, %1;" : "=f"(r) : "f"(x));
    return r;
}
__device__ __forceinline__ float fast_lg2(float x) {
    float r;
    asm("lg2.approx.f32 %0, %1;" : "=f"(r) : "f"(x));
    return r;
}
#define LDSM4(r0,r1,r2,r3,addr) \
    asm volatile("ldmatrix.sync.aligned.m8n8.x4.shared.b16 {%0,%1,%2,%3}, [%4];" \
        : "=r"(r0),"=r"(r1),"=r"(r2),"=r"(r3) : "r"(addr))
#define LDSM2(r0,r1,addr) \
    asm volatile("ldmatrix.sync.aligned.m8n8.x2.shared.b16 {%0,%1}, [%2];" \
        : "=r"(r0),"=r"(r1) : "r"(addr))
#define MMA16816(d,a,b) \
    asm volatile("mma.sync.aligned.m16n8k16.row.col.f32.bf16.bf16.f32 " \
        "{%0,%1,%2,%3},{%4,%5,%6,%7},{%8,%9},{%0,%1,%2,%3};" \
        : "+f"((d)[0]),"+f"((d)[1]),"+f"((d)[2]),"+f"((d)[3]) \
        : "r"((a)[0]),"r"((a)[1]),"r"((a)[2]),"r"((a)[3]),"r"((b)[0]),"r"((b)[1]))

// ---------------- kernel 1: fused convert + dual HMMA GEMM ----------------
// grid = (NCH, B_), block = 224, 2 CTAs/SM.
// Tiles keep 128-byte rows; stage parity p uses byte-half p of each row, so
// all physical offsets are the proven SW128 formulas XOR'ed with (p<<6).
__global__ void __launch_bounds__(NT, 2)
pm_mma_kernel(const float* __restrict__ xg, const float* __restrict__ mg)
{
    __shared__ __align__(1024) __nv_bfloat16 sA[MP*64];   // 14336 B
    __shared__ __align__(1024) __nv_bfloat16 sS[MP*64];   // 14336 B
    __shared__ __align__(1024) __nv_bfloat16 sB[NP*64];   //  7168 B

    const int b   = blockIdx.y;
    const int c   = blockIdx.x;
    const int tid = threadIdx.x;
    const int wid = tid >> 5;
    const int lid = tid & 31;

    // K split: 512 KB-units over 18 chunks -> 8x29 + 10x28
    const int nu = 28 + (c < 8 ? 1 : 0);
    const int u0 = c * 28 + (c < 8 ? c : 8);

    // zero smem once (pad rows + both parities stay zero until written)
    for (int i = tid; i < MP*64/8; i += NT) {
        reinterpret_cast<uint4*>(sA)[i] = make_uint4(0,0,0,0);
        reinterpret_cast<uint4*>(sS)[i] = make_uint4(0,0,0,0);
    }
    for (int i = tid; i < NP*64/8; i += NT)
        reinterpret_cast<uint4*>(sB)[i] = make_uint4(0,0,0,0);
    __syncthreads();

    const uint32_t sA32 = smem_u32(sA);
    const uint32_t sS32 = smem_u32(sS);
    const uint32_t sB32 = smem_u32(sB);

    // ---- ldmatrix address precompute (identical formulas to passing kernel) ----
    const int mbase = wid * 16;
    const int arow  = mbase + (lid & 15);
    const uint32_t axor = (uint32_t)((arow & 7) << 4);
    const uint32_t akb0 = (uint32_t)((lid >> 4) << 4);
    // per-ks A offsets (ks in {0,1}): row*128 + ((ks*32 + akb0) ^ axor)
    const uint32_t aoffk0 = (uint32_t)(arow * 128) + ((0u  + akb0) ^ axor);
    const uint32_t aoffk1 = (uint32_t)(arow * 128) + ((32u + akb0) ^ axor);
    const int bg = lid >> 3, br = lid & 7;
    const uint32_t bxor = (uint32_t)(br << 4);
    const uint32_t bkb0 = (uint32_t)((bg & 1) << 4);
    const uint32_t brow_base = (uint32_t)(((bg >> 1) * 8 + br) * 128);  // pair tiles
    const uint32_t brow6     = (uint32_t)((48 + br) * 128);             // tile 6

    // ---- loader slot precompute ----
    // x: 800 slots (100 rows x 8 float4), j<4 ; m: 400 slots, j<2
    const float* xp[4];
    uint32_t sxoff[4];  bool xact[4];
    #pragma unroll
    for (int j = 0; j < 4; j++) {
        int sl = tid + NT * j;
        xact[j] = sl < Q_ * (KB/4);
        int row = sl >> 3, c4 = sl & 7;
        xp[j] = xg + (size_t)b * Q_ * G_ + (size_t)row * G_ + u0 * KB + c4 * 4;
        sxoff[j] = (uint32_t)(row * 128) + (uint32_t)((c4 * 8) ^ ((row & 7) << 4));
    }
    const float* mp_[2];
    uint32_t smoff[2];  bool mact[2];
    #pragma unroll
    for (int j = 0; j < 2; j++) {
        int sl = tid + NT * j;
        mact[j] = sl < T_ * (KB/4);
        int row = sl >> 3, c4 = sl & 7;
        mp_[j] = mg + (size_t)b * T_ * G_ + (size_t)row * G_ + u0 * KB + c4 * 4;
        smoff[j] = (uint32_t)(row * 128) + (uint32_t)((c4 * 8) ^ ((row & 7) << 4));
    }

    float c1[7][4], c2[7][4];
    #pragma unroll
    for (int j = 0; j < 7; j++)
        #pragma unroll
        for (int u = 0; u < 4; u++) { c1[j][u] = 0.f; c2[j][u] = 0.f; }
    float aSP[4], aSG[4], aM[2];
    #pragma unroll
    for (int j = 0; j < 4; j++) { aSP[j] = 0.f; aSG[j] = 0.f; }
    aM[0] = aM[1] = 0.f;

    // ---- prologue: prefetch stage 0 ----
    float4 vx[4], vm[2];
    #pragma unroll
    for (int j = 0; j < 4; j++)
        if (xact[j]) vx[j] = *reinterpret_cast<const float4*>(xp[j]);
    #pragma unroll
    for (int j = 0; j < 2; j++)
        if (mact[j]) vm[j] = *reinterpret_cast<const float4*>(mp_[j]);

    for (int s = 0; s < nu; s++) {
        const uint32_t p64 = (uint32_t)((s & 1) << 6);

        // ---- convert + STS (fused, no staging regs). Safe: parity buffer. ----
        #pragma unroll
        for (int j = 0; j < 4; j++) {
            if (!xact[j]) continue;
            float f[4] = { vx[j].x, vx[j].y, vx[j].z, vx[j].w };
            float sg[4];
            #pragma unroll
            for (int u = 0; u < 4; u++) {
                float x    = f[u];
                float t    = fast_tanh(0.5f * x);
                float sig  = fmaf(0.5f, t, 0.5f);
                float siga = fmaf(0.5f, fabsf(t), 0.5f);   // sigmoid(|x|)
                sg[u] = sig;
                aSG[j] += sig;
                aSP[j] += fmaxf(x, 0.f) - 0.69314718056f * fast_lg2(siga);
            }
            uint32_t off = sxoff[j] ^ p64;
            *reinterpret_cast<uint2*>(reinterpret_cast<char*>(sA) + off) =
                make_uint2(bf2(f[0], f[1]), bf2(f[2], f[3]));
            *reinterpret_cast<uint2*>(reinterpret_cast<char*>(sS) + off) =
                make_uint2(bf2(sg[0], sg[1]), bf2(sg[2], sg[3]));
        }
        #pragma unroll
        for (int j = 0; j < 2; j++) {
            if (!mact[j]) continue;
            aM[j] += vm[j].x + vm[j].y + vm[j].z + vm[j].w;
            uint32_t off = smoff[j] ^ p64;
            *reinterpret_cast<uint2*>(reinterpret_cast<char*>(sB) + off) =
                make_uint2(bf2(vm[j].x, vm[j].y), bf2(vm[j].z, vm[j].w));
        }

        // ---- prefetch next stage ----
        if (s + 1 < nu) {
            #pragma unroll
            for (int j = 0; j < 4; j++) {
                xp[j] += KB;
                if (xact[j]) vx[j] = *reinterpret_cast<const float4*>(xp[j]);
            }
            #pragma unroll
            for (int j = 0; j < 2; j++) {
                mp_[j] += KB;
                if (mact[j]) vm[j] = *reinterpret_cast<const float4*>(mp_[j]);
            }
        }

        __syncthreads();   // single barrier per stage (double-buffered tiles)

        // ---- MMA: 2 k-steps x 7 n-tiles x 2 gemms ----
        #pragma unroll
        for (int ks = 0; ks < 2; ks++) {
            const uint32_t aad = ((ks ? aoffk1 : aoffk0) ^ p64);
            uint32_t ax[4], as2[4];
            LDSM4(ax[0],  ax[1],  ax[2],  ax[3],  sA32 + aad);
            LDSM4(as2[0], as2[1], as2[2], as2[3], sS32 + aad);

            uint32_t bf[7][2];
            const uint32_t binner = (((uint32_t)(ks * 32) + bkb0) ^ bxor) ^ p64;
            #pragma unroll
            for (int p3 = 0; p3 < 3; p3++) {
                int j = p3 * 2;
                uint32_t ad = brow_base + (uint32_t)(j * 8 * 128) + binner;
                LDSM4(bf[j][0], bf[j][1], bf[j+1][0], bf[j+1][1], sB32 + ad);
            }
            {   // n-tile 6 (x2)
                uint32_t inner6 = (((uint32_t)(ks * 32) + bkb0) ^ bxor) ^ p64;
                LDSM2(bf[6][0], bf[6][1], sB32 + brow6 + inner6);
            }
            #pragma unroll
            for (int j = 0; j < 7; j++) {
                MMA16816(c1[j], ax,  bf[j]);
                MMA16816(c2[j], as2, bf[j]);
            }
        }
    }

    // ---- row-stat reduction (8 slots per row -> 8-lane shfl, unconditional) ----
    #pragma unroll
    for (int j = 0; j < 4; j++) {
        float v1 = aSP[j], v2 = aSG[j];
        #pragma unroll
        for (int o = 4; o > 0; o >>= 1) {
            v1 += __shfl_xor_sync(0xffffffffu, v1, o);
            v2 += __shfl_xor_sync(0xffffffffu, v2, o);
        }
        int sl = tid + NT * j;
        if (xact[j] && (lid & 7) == 0) {
            g_SnegP[(b * NCH + c) * Q_ + (sl >> 3)] = v1;
            g_SsigP[(b * NCH + c) * Q_ + (sl >> 3)] = v2;
        }
    }
    #pragma unroll
    for (int j = 0; j < 2; j++) {
        float v = aM[j];
        #pragma unroll
        for (int o = 4; o > 0; o >>= 1)
            v += __shfl_xor_sync(0xffffffffu, v, o);
        int sl = tid + NT * j;
        if (mact[j] && (lid & 7) == 0)
            g_SmP[(b * NCH + c) * T_ + (sl >> 3)] = v;
    }

    // ---- C epilogue: direct stores (disjoint per CTA, padded layout) ----
    {
        const int r0 = mbase + (lid >> 2);
        const int cb = (lid & 3) * 2;
        float* p1 = g_P1 + ((size_t)((b * NCH + c) * MP + r0)) * NP;
        float* p2 = g_P2 + ((size_t)((b * NCH + c) * MP + r0)) * NP;
        #pragma unroll
        for (int j = 0; j < 7; j++) {
            int col = j * 8 + cb;
            *reinterpret_cast<float2*>(p1 + col)          = make_float2(c1[j][0], c1[j][1]);
            *reinterpret_cast<float2*>(p1 + 8*NP + col)   = make_float2(c1[j][2], c1[j][3]);
            *reinterpret_cast<float2*>(p2 + col)          = make_float2(c2[j][0], c2[j][1]);
            *reinterpret_cast<float2*>(p2 + 8*NP + col)   = make_float2(c2[j][2], c2[j][3]);
        }
    }
}

// ---------------- kernel 2: reduce row-stat partials ----------------
__global__ void stat_reduce_kernel() {
    int i = blockIdx.x * blockDim.x + threadIdx.x;
    if (i < B_*Q_) {
        int b = i / Q_, q = i % Q_;
        float s1 = 0.f, s2 = 0.f;
        #pragma unroll
        for (int c = 0; c < NCH; c++) {
            s1 += g_SnegP[(b * NCH + c) * Q_ + q];
            s2 += g_SsigP[(b * NCH + c) * Q_ + q];
        }
        g_Sneg[i] = s1; g_Ssig[i] = s2;
    } else if (i < B_*Q_ + B_*T_) {
        int k = i - B_*Q_;
        int b = k / T_, t = k % T_;
        float s = 0.f;
        #pragma unroll
        for (int c = 0; c < NCH; c++)
            s += g_SmP[(b * NCH + c) * T_ + t];
        g_Sm[k] = s;
    }
}

// ---------------- kernel 3: reduce C partials + class cost (t-pairs) ----------------
#define TPAIRS (T_/2)
__global__ void combine_kernel(const float* __restrict__ clsq,
                               const int* __restrict__ labw,
                               float* __restrict__ out)
{
    int idx = blockIdx.x * blockDim.x + threadIdx.x;
    if (idx >= B_*Q_*TPAIRS) return;
    int p = idx % TPAIRS;
    int q = (idx / TPAIRS) % Q_;
    int b = idx / (TPAIRS*Q_);
    int t0 = 2 * p;

    float2 D1 = make_float2(0.f, 0.f), D2 = make_float2(0.f, 0.f);
    #pragma unroll
    for (int c = 0; c < NCH; c++) {
        size_t o = ((size_t)((b * NCH + c) * MP + q)) * NP + t0;
        float2 v1 = *reinterpret_cast<const float2*>(g_P1 + o);
        float2 v2 = *reinterpret_cast<const float2*>(g_P2 + o);
        D1.x += v1.x; D1.y += v1.y;
        D2.x += v2.x; D2.y += v2.y;
    }

    // label dtype detect (int64 high words zero for labels < 2^31)
    bool is64 = true;
    #pragma unroll
    for (int j = 0; j < 8; j++) is64 &= (labw[2*j + 1] == 0);
    int li0 = b * T_ + t0;
    int l0 = is64 ? labw[2 * li0]       : labw[li0];
    int l1 = is64 ? labw[2 * (li0 + 1)] : labw[li0 + 1];

    const float* cl = clsq + (size_t)(b * Q_ + q) * L_;
    float mx = cl[0];
    #pragma unroll
    for (int k = 1; k < L_; k++) mx = fmaxf(mx, cl[k]);
    float ssum = 0.f;
    #pragma unroll
    for (int k = 0; k < L_; k++) ssum += __expf(cl[k] - mx);
    float inv = __fdividef(1.f, ssum);
    float prob0 = __expf(cl[l0] - mx) * inv;
    float prob1 = __expf(cl[l1] - mx) * inv;

    float Sneg = g_Sneg[b * Q_ + q];
    float Ssig = g_Ssig[b * Q_ + q];
    float Sm0  = g_Sm[li0];
    float Sm1  = g_Sm[li0 + 1];

    const float invG = 1.0f / (float)G_;
    float o0 = (Sneg - D1.x) * invG - prob0
             + 1.0f - (2.0f * D2.x + 1.0f) * __fdividef(1.f, Ssig + Sm0 + 1.0f);
    float o1 = (Sneg - D1.y) * invG - prob1
             + 1.0f - (2.0f * D2.y + 1.0f) * __fdividef(1.f, Ssig + Sm1 + 1.0f);
    *reinterpret_cast<float2*>(out + (size_t)(b * Q_ + q) * T_ + t0) =
        make_float2(o0, o1);
}

// ---------------- launch ----------------
extern "C" void kernel_launch(void* const* d_in, const int* in_sizes, int n_in,
                              void* d_out, int out_size)
{
    const float* x   = (const float*)d_in[0];   // [16,100,16384] f32
    const float* cq  = (const float*)d_in[1];   // [16,100,21]    f32
    const float* m   = (const float*)d_in[2];   // [16,50,16384]  f32
    const int*   lab = (const int*)d_in[3];     // [16,50] labels

    dim3 grid(NCH, B_);
    pm_mma_kernel<<<grid, NT>>>(x, m);

    stat_reduce_kernel<<<(B_*Q_ + B_*T_ + 255) / 256, 256>>>();

    combine_kernel<<<(B_*Q_*TPAIRS + 255) / 256, 256>>>(cq, lab, (float*)d_out);
}

// round 6
// speedup vs baseline: 1.6901x; 1.0368x over previous
#include <cuda_runtime.h>
#include <cuda_bf16.h>
#include <stdint.h>

#define B_ 16
#define Q_ 100
#define G_ 16384
#define T_ 50
#define L_ 21
#define NCH 18
#define KB 32          // k elements per stage (half of a 128B row; double-buffered)
#define MP 112         // padded M per GEMM (7 warps x 16)
#define NP 56          // padded N (7 n-tiles x 8)
#define NT 448         // threads (14 warps: 7 for x-GEMM, 7 for sigma-GEMM)

// ---------------- device scratch (module statics, allocation-free) ----------------
__device__ float g_P1[B_*NCH*MP*NP];     // partial dot(x, m)
__device__ float g_P2[B_*NCH*MP*NP];     // partial dot(sig(x), m)
__device__ float g_SnegP[B_*NCH*Q_];     // partial softplus row sums
__device__ float g_SsigP[B_*NCH*Q_];     // partial sigmoid row sums
__device__ float g_SmP[B_*NCH*T_];       // partial mask row sums
__device__ float g_Sneg[B_*Q_];
__device__ float g_Ssig[B_*Q_];
__device__ float g_Sm[B_*T_];

// ---------------- helpers ----------------
__device__ __forceinline__ uint32_t smem_u32(const void* p) {
    uint32_t a;
    asm("{ .reg .u64 t; cvta.to.shared.u64 t, %1; cvt.u32.u64 %0, t; }"
        : "=r"(a) : "l"(p));
    return a;
}
__device__ __forceinline__ uint32_t bf2(float lo, float hi) {
    uint32_t r;
    asm("cvt.rn.bf16x2.f32 %0, %1, %2;" : "=r"(r) : "f"(hi), "f"(lo));
    return r;
}
__device__ __forceinline__ float fast_tanh(float x) {
    float r;
    asm("tanh.approx.f32 %0, %1;" : "=f"(r) : "f"(x));
    return r;
}
__device__ __forceinline__ float fast_lg2(float x) {
    float r;
    asm("lg2.approx.f32 %0, %1;" : "=f"(r) : "f"(x));
    return r;
}
#define LDSM4(r0,r1,r2,r3,addr) \
    asm volatile("ldmatrix.sync.aligned.m8n8.x4.shared.b16 {%0,%1,%2,%3}, [%4];" \
        : "=r"(r0),"=r"(r1),"=r"(r2),"=r"(r3) : "r"(addr))
#define LDSM2(r0,r1,addr) \
    asm volatile("ldmatrix.sync.aligned.m8n8.x2.shared.b16 {%0,%1}, [%2];" \
        : "=r"(r0),"=r"(r1) : "r"(addr))
#define MMA16816(d,a,b0,b1) \
    asm volatile("mma.sync.aligned.m16n8k16.row.col.f32.bf16.bf16.f32 " \
        "{%0,%1,%2,%3},{%4,%5,%6,%7},{%8,%9},{%0,%1,%2,%3};" \
        : "+f"((d)[0]),"+f"((d)[1]),"+f"((d)[2]),"+f"((d)[3]) \
        : "r"((a)[0]),"r"((a)[1]),"r"((a)[2]),"r"((a)[3]),"r"(b0),"r"(b1))

// ---------------- kernel 1: fused convert + concatenated HMMA GEMM ----------------
// grid = (NCH, B_), block = 448, 2 CTAs/SM.
// Single logical GEMM M=224 (x rows + sigma rows) x N=56: warps 0-6 -> x-GEMM,
// warps 7-13 -> sigma-GEMM. 28 accumulator regs/thread.
__global__ void __launch_bounds__(NT, 2)
pm_mma_kernel(const float* __restrict__ xg, const float* __restrict__ mg)
{
    __shared__ __align__(1024) __nv_bfloat16 sA[MP*64];   // x     14336 B
    __shared__ __align__(1024) __nv_bfloat16 sS[MP*64];   // sigma 14336 B
    __shared__ __align__(1024) __nv_bfloat16 sB[NP*64];   // m      7168 B

    const int b   = blockIdx.y;
    const int c   = blockIdx.x;
    const int tid = threadIdx.x;
    const int wid = tid >> 5;
    const int lid = tid & 31;

    // K split: 512 KB-units over 18 chunks -> 8x29 + 10x28
    const int nu = 28 + (c < 8 ? 1 : 0);
    const int u0 = c * 28 + (c < 8 ? c : 8);

    // zero smem once (pad rows + both parities stay zero until written)
    for (int i = tid; i < MP*64/8; i += NT) {
        reinterpret_cast<uint4*>(sA)[i] = make_uint4(0,0,0,0);
        reinterpret_cast<uint4*>(sS)[i] = make_uint4(0,0,0,0);
    }
    for (int i = tid; i < NP*64/8; i += NT)
        reinterpret_cast<uint4*>(sB)[i] = make_uint4(0,0,0,0);
    __syncthreads();

    const uint32_t sB32 = smem_u32(sB);

    // ---- warp -> (gemm half, m-row base) ----
    const int gsel  = (wid >= 7);              // 0: x-GEMM, 1: sigma-GEMM
    const int wloc  = gsel ? (wid - 7) : wid;
    const uint32_t sAS32 = gsel ? smem_u32(sS) : smem_u32(sA);

    // ---- ldmatrix address precompute (proven formulas) ----
    const int mbase = wloc * 16;
    const int arow  = mbase + (lid & 15);
    const uint32_t axor = (uint32_t)((arow & 7) << 4);
    const uint32_t akb0 = (uint32_t)((lid >> 4) << 4);
    const uint32_t aoffk0 = (uint32_t)(arow * 128) + ((0u  + akb0) ^ axor);
    const uint32_t aoffk1 = (uint32_t)(arow * 128) + ((32u + akb0) ^ axor);
    const int bg = lid >> 3, br = lid & 7;
    const uint32_t bxor = (uint32_t)(br << 4);
    const uint32_t bkb0 = (uint32_t)((bg & 1) << 4);
    const uint32_t brow_base = (uint32_t)(((bg >> 1) * 8 + br) * 128);  // pair tiles
    const uint32_t brow6     = (uint32_t)((48 + br) * 128);             // tile 6

    // ---- loader slot precompute ----
    // x: 800 slots (100 rows x 8 float4), 2 slots/thread ; m: 400 slots, 1 slot
    const float* xp[2];
    uint32_t sxoff[2];  bool xact[2];
    #pragma unroll
    for (int j = 0; j < 2; j++) {
        int sl = tid + NT * j;
        xact[j] = sl < Q_ * (KB/4);
        int row = sl >> 3, c4 = sl & 7;
        xp[j] = xg + (size_t)b * Q_ * G_ + (size_t)row * G_ + u0 * KB + c4 * 4;
        sxoff[j] = (uint32_t)(row * 128) + (uint32_t)((c4 * 8) ^ ((row & 7) << 4));
    }
    const bool mact = tid < T_ * (KB/4);
    const float* mp_ = mg + (size_t)b * T_ * G_
                     + (size_t)(tid >> 3) * G_ + u0 * KB + (tid & 7) * 4;
    const uint32_t smoff = (uint32_t)((tid >> 3) * 128)
                         + (uint32_t)(((tid & 7) * 8) ^ (((tid >> 3) & 7) << 4));

    float cc[7][4];
    #pragma unroll
    for (int j = 0; j < 7; j++)
        #pragma unroll
        for (int u = 0; u < 4; u++) cc[j][u] = 0.f;
    float aSP[2] = {0.f, 0.f}, aSG[2] = {0.f, 0.f}, aM = 0.f;

    // ---- prologue: prefetch stage 0 ----
    float4 vx[2], vm;
    #pragma unroll
    for (int j = 0; j < 2; j++)
        if (xact[j]) vx[j] = *reinterpret_cast<const float4*>(xp[j]);
    if (mact) vm = *reinterpret_cast<const float4*>(mp_);

    for (int s = 0; s < nu; s++) {
        const uint32_t p64 = (uint32_t)((s & 1) << 6);

        // ---- convert + STS (fused; parity buffer makes it WAR-safe) ----
        #pragma unroll
        for (int j = 0; j < 2; j++) {
            if (!xact[j]) continue;
            float f[4] = { vx[j].x, vx[j].y, vx[j].z, vx[j].w };
            float sg[4];
            #pragma unroll
            for (int u = 0; u < 4; u++) {
                float x    = f[u];
                float t    = fast_tanh(0.5f * x);
                float sig  = fmaf(0.5f, t, 0.5f);
                float siga = fmaf(0.5f, fabsf(t), 0.5f);   // sigmoid(|x|)
                sg[u] = sig;
                aSG[j] += sig;
                aSP[j] += fmaxf(x, 0.f) - 0.69314718056f * fast_lg2(siga);
            }
            uint32_t off = sxoff[j] ^ p64;
            *reinterpret_cast<uint2*>(reinterpret_cast<char*>(sA) + off) =
                make_uint2(bf2(f[0], f[1]), bf2(f[2], f[3]));
            *reinterpret_cast<uint2*>(reinterpret_cast<char*>(sS) + off) =
                make_uint2(bf2(sg[0], sg[1]), bf2(sg[2], sg[3]));
        }
        if (mact) {
            aM += vm.x + vm.y + vm.z + vm.w;
            uint32_t off = smoff ^ p64;
            *reinterpret_cast<uint2*>(reinterpret_cast<char*>(sB) + off) =
                make_uint2(bf2(vm.x, vm.y), bf2(vm.z, vm.w));
        }

        // ---- prefetch next stage ----
        if (s + 1 < nu) {
            #pragma unroll
            for (int j = 0; j < 2; j++) {
                xp[j] += KB;
                if (xact[j]) vx[j] = *reinterpret_cast<const float4*>(xp[j]);
            }
            mp_ += KB;
            if (mact) vm = *reinterpret_cast<const float4*>(mp_);
        }

        __syncthreads();   // single barrier per stage (double-buffered tiles)

        // ---- MMA: 2 k-steps x 7 n-tiles (one GEMM half per warp) ----
        #pragma unroll
        for (int ks = 0; ks < 2; ks++) {
            const uint32_t aad = ((ks ? aoffk1 : aoffk0) ^ p64);
            uint32_t ax[4];
            LDSM4(ax[0], ax[1], ax[2], ax[3], sAS32 + aad);

            const uint32_t binner = (((uint32_t)(ks * 32) + bkb0) ^ bxor) ^ p64;
            #pragma unroll
            for (int p3 = 0; p3 < 3; p3++) {
                uint32_t bf0, bf1, bf2r, bf3;
                uint32_t ad = brow_base + (uint32_t)(p3 * 2048) + binner;
                LDSM4(bf0, bf1, bf2r, bf3, sB32 + ad);
                MMA16816(cc[p3*2],     ax, bf0,  bf1);
                MMA16816(cc[p3*2 + 1], ax, bf2r, bf3);
            }
            {   // n-tile 6 (x2)
                uint32_t bf0, bf1;
                LDSM2(bf0, bf1, sB32 + brow6 + binner);
                MMA16816(cc[6], ax, bf0, bf1);
            }
        }
    }

    // ---- row-stat reduction (8 slots per row -> 8-lane shfl) ----
    #pragma unroll
    for (int j = 0; j < 2; j++) {
        float v1 = aSP[j], v2 = aSG[j];
        #pragma unroll
        for (int o = 4; o > 0; o >>= 1) {
            v1 += __shfl_xor_sync(0xffffffffu, v1, o);
            v2 += __shfl_xor_sync(0xffffffffu, v2, o);
        }
        int sl = tid + NT * j;
        if (xact[j] && (lid & 7) == 0) {
            g_SnegP[(b * NCH + c) * Q_ + (sl >> 3)] = v1;
            g_SsigP[(b * NCH + c) * Q_ + (sl >> 3)] = v2;
        }
    }
    {
        float v = aM;
        #pragma unroll
        for (int o = 4; o > 0; o >>= 1)
            v += __shfl_xor_sync(0xffffffffu, v, o);
        if (mact && (lid & 7) == 0)
            g_SmP[(b * NCH + c) * T_ + (tid >> 3)] = v;
    }

    // ---- C epilogue: direct stores (disjoint per CTA & per GEMM half) ----
    {
        const int r0 = mbase + (lid >> 2);
        const int cb = (lid & 3) * 2;
        float* gp = (gsel ? g_P2 : g_P1)
                  + ((size_t)((b * NCH + c) * MP + r0)) * NP;
        #pragma unroll
        for (int j = 0; j < 7; j++) {
            int col = j * 8 + cb;
            *reinterpret_cast<float2*>(gp + col)        = make_float2(cc[j][0], cc[j][1]);
            *reinterpret_cast<float2*>(gp + 8*NP + col) = make_float2(cc[j][2], cc[j][3]);
        }
    }
}

// ---------------- kernel 2: reduce row-stat partials ----------------
__global__ void stat_reduce_kernel() {
    int i = blockIdx.x * blockDim.x + threadIdx.x;
    if (i < B_*Q_) {
        int b = i / Q_, q = i % Q_;
        float s1 = 0.f, s2 = 0.f;
        #pragma unroll
        for (int c = 0; c < NCH; c++) {
            s1 += g_SnegP[(b * NCH + c) * Q_ + q];
            s2 += g_SsigP[(b * NCH + c) * Q_ + q];
        }
        g_Sneg[i] = s1; g_Ssig[i] = s2;
    } else if (i < B_*Q_ + B_*T_) {
        int k = i - B_*Q_;
        int b = k / T_, t = k % T_;
        float s = 0.f;
        #pragma unroll
        for (int c = 0; c < NCH; c++)
            s += g_SmP[(b * NCH + c) * T_ + t];
        g_Sm[k] = s;
    }
}

// ---------------- kernel 3: reduce C partials + class cost (t-pairs) ----------------
#define TPAIRS (T_/2)
__global__ void combine_kernel(const float* __restrict__ clsq,
                               const int* __restrict__ labw,
                               float* __restrict__ out)
{
    int idx = blockIdx.x * blockDim.x + threadIdx.x;
    if (idx >= B_*Q_*TPAIRS) return;
    int p = idx % TPAIRS;
    int q = (idx / TPAIRS) % Q_;
    int b = idx / (TPAIRS*Q_);
    int t0 = 2 * p;

    float2 D1 = make_float2(0.f, 0.f), D2 = make_float2(0.f, 0.f);
    #pragma unroll
    for (int c = 0; c < NCH; c++) {
        size_t o = ((size_t)((b * NCH + c) * MP + q)) * NP + t0;
        float2 v1 = *reinterpret_cast<const float2*>(g_P1 + o);
        float2 v2 = *reinterpret_cast<const float2*>(g_P2 + o);
        D1.x += v1.x; D1.y += v1.y;
        D2.x += v2.x; D2.y += v2.y;
    }

    // label dtype detect (int64 high words zero for labels < 2^31)
    bool is64 = true;
    #pragma unroll
    for (int j = 0; j < 8; j++) is64 &= (labw[2*j + 1] == 0);
    int li0 = b * T_ + t0;
    int l0 = is64 ? labw[2 * li0]       : labw[li0];
    int l1 = is64 ? labw[2 * (li0 + 1)] : labw[li0 + 1];

    const float* cl = clsq + (size_t)(b * Q_ + q) * L_;
    float mx = cl[0];
    #pragma unroll
    for (int k = 1; k < L_; k++) mx = fmaxf(mx, cl[k]);
    float ssum = 0.f;
    #pragma unroll
    for (int k = 0; k < L_; k++) ssum += __expf(cl[k] - mx);
    float inv = __fdividef(1.f, ssum);
    float prob0 = __expf(cl[l0] - mx) * inv;
    float prob1 = __expf(cl[l1] - mx) * inv;

    float Sneg = g_Sneg[b * Q_ + q];
    float Ssig = g_Ssig[b * Q_ + q];
    float Sm0  = g_Sm[li0];
    float Sm1  = g_Sm[li0 + 1];

    const float invG = 1.0f / (float)G_;
    float o0 = (Sneg - D1.x) * invG - prob0
             + 1.0f - (2.0f * D2.x + 1.0f) * __fdividef(1.f, Ssig + Sm0 + 1.0f);
    float o1 = (Sneg - D1.y) * invG - prob1
             + 1.0f - (2.0f * D2.y + 1.0f) * __fdividef(1.f, Ssig + Sm1 + 1.0f);
    *reinterpret_cast<float2*>(out + (size_t)(b * Q_ + q) * T_ + t0) =
        make_float2(o0, o1);
}

// ---------------- launch ----------------
extern "C" void kernel_launch(void* const* d_in, const int* in_sizes, int n_in,
                              void* d_out, int out_size)
{
    const float* x   = (const float*)d_in[0];   // [16,100,16384] f32
    const float* cq  = (const float*)d_in[1];   // [16,100,21]    f32
    const float* m   = (const float*)d_in[2];   // [16,50,16384]  f32
    const int*   lab = (const int*)d_in[3];     // [16,50] labels

    dim3 grid(NCH, B_);
    pm_mma_kernel<<<grid, NT>>>(x, m);

    stat_reduce_kernel<<<(B_*Q_ + B_*T_ + 255) / 256, 256>>>();

    combine_kernel<<<(B_*Q_*TPAIRS + 255) / 256, 256>>>(cq, lab, (float*)d_out);
}